// round 12
// baseline (speedup 1.0000x reference)
#include <cuda_runtime.h>
#include <math.h>
#include <stdint.h>

#define Nn 50000
#define Ee 600000
#define Rr 64
#define Vv 49936
#define HDim 128
#define NHEAD 4
#define EDim 8
#define NCHUNK 98
#define GB 6250    // gather blocks per type
#define EB 2344    // edge blocks per type
#define MB 391     // gemm blocks per type

// ---------------- scratch ----------------------------------------------------
__device__ float g_h[3][(size_t)Nn * HDim];
__device__ float g_x2[3][(size_t)Nn * HDim];
__device__ float g_acc[(size_t)Nn * HDim];
__device__ float g_ssrc[3][Nn * NHEAD];
__device__ float g_sdst[3][Nn * NHEAD];
__device__ float g_aloop[3][Nn * NHEAD];
__device__ float g_ssrc2[3][Nn];
__device__ float g_sdst2[3][Nn];
__device__ float g_aloop2[3][Nn];
__device__ int   g_deg[3][Nn];
__device__ int   g_cursor[3][Nn];
__device__ int   g_rowptr[3][Nn + 1];
__device__ int   g_bsum[3][NCHUNK];
__device__ int2  g_csr[3][Ee];          // packed (src, eid)
__device__ float g_edot1[3][(size_t)Ee * 4];
__device__ float g_edot2[3][Ee];
__device__ float g_val1[3][(size_t)Ee * 4];  // CSR-ordered ssrc1[src]+edot1[eid], per head
__device__ float g_val2[3][Ee];              // CSR-ordered ssrc2[src]+edot2[eid]
__device__ float g_scores[Vv];
__device__ float g_pmax[Rr], g_pden[Rr];
__device__ int   g_pcnt[Rr];
__device__ float g_pooled[Rr * HDim];
__device__ float g_q1[Rr * HDim];
__device__ float g_q2[Rr * 64];
__device__ float g_gate[3], g_wts[3];
__device__ float g_Wt[3][2][HDim];
__device__ float g_v1[3][NHEAD][EDim];
__device__ float g_v2[3][EDim];
__device__ float g_edl1[3][NHEAD];
__device__ float g_edl2[3];
__device__ float g_easum[3][EDim];
__device__ float g_was1[3][NHEAD][9];
__device__ float g_wad1[3][NHEAD][9];
__device__ float g_cA1[3][2][NHEAD];
__device__ float g_cD1[3][2][NHEAD];
__device__ float g_wa2[3][HDim];
__device__ float g_wd2[3][HDim];

__device__ __forceinline__ uint32_t f2tf32(float f) {
    uint32_t u; asm("cvt.rna.tf32.f32 %0, %1;" : "=r"(u) : "f"(f)); return u;
}

#define MMA_TF32(d, a, b) \
    asm volatile("mma.sync.aligned.m16n8k8.row.col.f32.tf32.tf32.f32 " \
        "{%0,%1,%2,%3}, {%4,%5,%6,%7}, {%8,%9}, {%0,%1,%2,%3};" \
        : "+f"(d[0]), "+f"(d[1]), "+f"(d[2]), "+f"(d[3]) \
        : "r"(a[0]), "r"(a[1]), "r"(a[2]), "r"(a[3]), "r"(b[0]), "r"(b[1]))

// ---------------- init + setup ------------------------------------------------
__global__ void k_init() {
    int i = blockIdx.x * 256 + threadIdx.x;
    if (i < 3 * Nn) ((int*)g_deg)[i] = 0;
    if (i < 24) ((float*)g_easum)[i] = 0.f;
}

__global__ void k_easum(const float* __restrict__ ea0, const float* __restrict__ ea1,
                        const float* __restrict__ ea2) {
    const float* ea = blockIdx.y == 0 ? ea0 : (blockIdx.y == 1 ? ea1 : ea2);
    __shared__ float s[EDim];
    if (threadIdx.x < EDim) s[threadIdx.x] = 0.f;
    __syncthreads();
    float loc[EDim];
#pragma unroll
    for (int k = 0; k < EDim; k++) loc[k] = 0.f;
    int base = blockIdx.x * 4096;
    int lim = base + 4096; if (lim > Ee) lim = Ee;
    for (int e = base + threadIdx.x; e < lim; e += 256) {
        const float4* p = (const float4*)(ea + (size_t)e * 8);
        float4 a = p[0], b = p[1];
        loc[0] += a.x; loc[1] += a.y; loc[2] += a.z; loc[3] += a.w;
        loc[4] += b.x; loc[5] += b.y; loc[6] += b.z; loc[7] += b.w;
    }
#pragma unroll
    for (int k = 0; k < EDim; k++) atomicAdd(&s[k], loc[k]);
    __syncthreads();
    if (threadIdx.x < EDim) atomicAdd(&g_easum[blockIdx.y][threadIdx.x], s[threadIdx.x]);
}

__global__ void k_setup(const float* __restrict__ temb, const float* __restrict__ etg,
                        const float* __restrict__ eta, const float* __restrict__ W1,
                        const float* __restrict__ We1, const float* __restrict__ ae1,
                        const float* __restrict__ We2, const float* __restrict__ ae2,
                        const float* __restrict__ as1, const float* __restrict__ ad1,
                        const float* __restrict__ W2, const float* __restrict__ as2,
                        const float* __restrict__ ad2) {
    int t = threadIdx.x;
    if (t < 3) g_gate[t] = 1.f / (1.f + __expf(-etg[t]));
    if (t == 0) {
        float m = fmaxf(eta[0], fmaxf(eta[1], eta[2]));
        float e0 = __expf(eta[0] - m), e1 = __expf(eta[1] - m), e2 = __expf(eta[2] - m);
        float s = e0 + e1 + e2;
        g_wts[0] = e0 / s; g_wts[1] = e1 / s; g_wts[2] = e2 / s;
    }
    __syncthreads();
    for (int idx = t; idx < 3 * 2 * HDim; idx += 256) {
        int i = idx / (2 * HDim); int r = idx % (2 * HDim);
        int ty = r / HDim; int j = r % HDim;
        float s = 0.f;
        for (int k = 0; k < 32; k++)
            s += temb[ty * 32 + k] * W1[i * 41 * HDim + (9 + k) * HDim + j];
        g_Wt[i][ty][j] = s;
    }
    for (int idx = t; idx < 3 * NHEAD * EDim; idx += 256) {
        int i = idx / 32; int h = (idx % 32) / 8; int k = idx % 8;
        float s = 0.f;
        for (int c = 0; c < 32; c++)
            s += We1[i * EDim * HDim + k * HDim + h * 32 + c] * ae1[i * NHEAD * 32 + h * 32 + c];
        g_v1[i][h][k] = g_gate[i] * s;
    }
    for (int idx = t; idx < 3 * EDim; idx += 256) {
        int i = idx / 8; int k = idx % 8;
        float s = 0.f;
        for (int c = 0; c < HDim; c++)
            s += We2[i * EDim * HDim + k * HDim + c] * ae2[i * HDim + c];
        g_v2[i][k] = g_gate[i] * s;
    }
    for (int idx = t; idx < 108; idx += 256) {
        int i = idx / 36; int h = (idx % 36) / 9; int k = idx % 9;
        float sa = 0.f, sd = 0.f;
        for (int c = 0; c < 32; c++) {
            float w = W1[i * 41 * HDim + k * HDim + h * 32 + c];
            sa += w * as1[i * HDim + h * 32 + c];
            sd += w * ad1[i * HDim + h * 32 + c];
        }
        g_was1[i][h][k] = sa;
        g_wad1[i][h][k] = sd;
    }
    for (int idx = t; idx < 3 * HDim; idx += 256) {
        int i = idx / HDim; int k = idx % HDim;
        float sa = 0.f, sd = 0.f;
        for (int j = 0; j < HDim; j++) {
            float w = W2[(size_t)i * HDim * HDim + k * HDim + j];
            sa += w * as2[i * HDim + j];
            sd += w * ad2[i * HDim + j];
        }
        g_wa2[i][k] = sa;
        g_wd2[i][k] = sd;
    }
    __syncthreads();
    if (t < 12) {
        int i = t / 4, h = t % 4;
        float s = 0.f;
        for (int k = 0; k < EDim; k++) s += (g_easum[i][k] / (float)Ee) * g_v1[i][h][k];
        g_edl1[i][h] = s;
    }
    if (t >= 32 && t < 35) {
        int i = t - 32;
        float s = 0.f;
        for (int k = 0; k < EDim; k++) s += (g_easum[i][k] / (float)Ee) * g_v2[i][k];
        g_edl2[i] = s;
    }
    if (t >= 64 && t < 88) {
        int r = t - 64;
        int i = r / 8; int ty = (r % 8) / 4; int h = r % 4;
        float sa = 0.f, sd = 0.f;
        for (int c = 0; c < 32; c++) {
            float w = g_Wt[i][ty][h * 32 + c];
            sa += w * as1[i * HDim + h * 32 + c];
            sd += w * ad1[i * HDim + h * 32 + c];
        }
        g_cA1[i][ty][h] = sa;
        g_cD1[i][ty][h] = sd;
    }
}

// ---------------- CSR build ----------------------------------------------------
__global__ void k_deg(const int* __restrict__ ei0, const int* __restrict__ ei1,
                      const int* __restrict__ ei2) {
    const int* ei = blockIdx.y == 0 ? ei0 : (blockIdx.y == 1 ? ei1 : ei2);
    int e = blockIdx.x * 1024 + threadIdx.x;
    if (e < Ee) atomicAdd(&g_deg[blockIdx.y][ei[Ee + e]], 1);
}

__global__ void k_partial() {
    __shared__ int s[512];
    int ty = blockIdx.y;
    int t = threadIdx.x;
    int i = blockIdx.x * 512 + t;
    s[t] = (i < Nn) ? g_deg[ty][i] : 0;
    __syncthreads();
    for (int off = 256; off > 0; off >>= 1) {
        if (t < off) s[t] += s[t + off];
        __syncthreads();
    }
    if (t == 0) g_bsum[ty][blockIdx.x] = s[0];
}

__global__ void k_scanb() {
    int t = threadIdx.x;
    if (t < 3) {
        int s = 0;
        for (int b = 0; b < NCHUNK; b++) { int v = g_bsum[t][b]; g_bsum[t][b] = s; s += v; }
    }
}

__global__ void k_scan2() {
    __shared__ int s[512];
    int ty = blockIdx.y;
    int t = threadIdx.x;
    int i = blockIdx.x * 512 + t;
    int v = (i < Nn) ? g_deg[ty][i] : 0;
    s[t] = v;
    __syncthreads();
    for (int off = 1; off < 512; off <<= 1) {
        int x = 0;
        if (t >= off) x = s[t - off];
        __syncthreads();
        s[t] += x;
        __syncthreads();
    }
    int excl = s[t] - v + g_bsum[ty][blockIdx.x];
    if (i < Nn) {
        g_rowptr[ty][i] = excl;
        g_cursor[ty][i] = excl;
        if (i == Nn - 1) g_rowptr[ty][Nn] = excl + v;
    }
}

__global__ void k_fill(const int* __restrict__ ei0, const int* __restrict__ ei1,
                       const int* __restrict__ ei2) {
    int ty = blockIdx.y;
    const int* ei = ty == 0 ? ei0 : (ty == 1 ? ei1 : ei2);
    int e = blockIdx.x * 1024 + threadIdx.x;
    if (e >= Ee) return;
    int src = ei[e], dst = ei[Ee + e];
    int pos = atomicAdd(&g_cursor[ty][dst], 1);
    g_csr[ty][pos] = make_int2(src, e);
}

// per-edge attention edge-term dots
__global__ void k_edot(const float* __restrict__ ea0, const float* __restrict__ ea1,
                       const float* __restrict__ ea2) {
    int i = blockIdx.x / EB;
    int bx = blockIdx.x % EB;
    const float* ea = i == 0 ? ea0 : (i == 1 ? ea1 : ea2);
    int e = bx * 256 + threadIdx.x;
    if (e >= Ee) return;
    const float4* p = (const float4*)(ea + (size_t)e * 8);
    float4 a0 = p[0], a1 = p[1];
    float4 d1;
    {
        const float* v = g_v1[i][0];
        d1.x = a0.x*v[0]+a0.y*v[1]+a0.z*v[2]+a0.w*v[3]+a1.x*v[4]+a1.y*v[5]+a1.z*v[6]+a1.w*v[7];
    }
    {
        const float* v = g_v1[i][1];
        d1.y = a0.x*v[0]+a0.y*v[1]+a0.z*v[2]+a0.w*v[3]+a1.x*v[4]+a1.y*v[5]+a1.z*v[6]+a1.w*v[7];
    }
    {
        const float* v = g_v1[i][2];
        d1.z = a0.x*v[0]+a0.y*v[1]+a0.z*v[2]+a0.w*v[3]+a1.x*v[4]+a1.y*v[5]+a1.z*v[6]+a1.w*v[7];
    }
    {
        const float* v = g_v1[i][3];
        d1.w = a0.x*v[0]+a0.y*v[1]+a0.z*v[2]+a0.w*v[3]+a1.x*v[4]+a1.y*v[5]+a1.z*v[6]+a1.w*v[7];
    }
    ((float4*)g_edot1[i])[e] = d1;
    const float* v = g_v2[i];
    g_edot2[i][e] = a0.x*v[0]+a0.y*v[1]+a0.z*v[2]+a0.w*v[3]+a1.x*v[4]+a1.y*v[5]+a1.z*v[6]+a1.w*v[7];
}

// ---------------- layer 1: h projection ----------------------------------------
__global__ void k_projA(const float* __restrict__ nf, const int* __restrict__ ntype,
                        const float* __restrict__ W1) {
    int i = blockIdx.y;
    const float* W1i = W1 + (size_t)i * 41 * HDim;
    int j = threadIdx.x;
    float w[9];
#pragma unroll
    for (int k = 0; k < 9; k++) w[k] = W1i[k * HDim + j];
    float wt0 = g_Wt[i][0][j], wt1 = g_Wt[i][1][j];
    float* hout = g_h[i];
    int nb = blockIdx.x * 4;
#pragma unroll
    for (int nn = 0; nn < 4; nn++) {
        int n = nb + nn;
        const float* row = nf + (size_t)n * 9;
        float acc = ntype[n] ? wt1 : wt0;
#pragma unroll
        for (int k = 0; k < 9; k++) acc += row[k] * w[k];
        hout[(size_t)n * HDim + j] = acc;
    }
}

__global__ void k_sattn1(const float* __restrict__ nf, const int* __restrict__ ntype) {
    int n = blockIdx.x * 256 + threadIdx.x;
    if (n >= Nn) return;
    float f[9];
#pragma unroll
    for (int k = 0; k < 9; k++) f[k] = nf[(size_t)n * 9 + k];
    int ty = ntype[n];
#pragma unroll
    for (int i = 0; i < 3; i++) {
#pragma unroll
        for (int h = 0; h < 4; h++) {
            float ss = g_cA1[i][ty][h];
            float sd = g_cD1[i][ty][h];
#pragma unroll
            for (int k = 0; k < 9; k++) {
                ss += f[k] * g_was1[i][h][k];
                sd += f[k] * g_wad1[i][h][k];
            }
            g_ssrc[i][n * 4 + h] = ss;
            g_sdst[i][n * 4 + h] = sd;
            float a = ss + sd + g_edl1[i][h];
            a = a > 0.f ? a : 0.2f * a;
            g_aloop[i][n * 4 + h] = a;
        }
    }
}

// CSR-ordered val1 = ssrc1[src] + edot1[eid]  (per head, float4)
__global__ void k_prep1() {
    int i = blockIdx.x / EB;
    int bx = blockIdx.x % EB;
    int pos = bx * 256 + threadIdx.x;
    if (pos >= Ee) return;
    int2 c = g_csr[i][pos];
    float4 s = ((const float4*)g_ssrc[i])[c.x];
    float4 d = ((const float4*)g_edot1[i])[c.y];
    float4 v;
    v.x = s.x + d.x; v.y = s.y + d.y; v.z = s.z + d.z; v.w = s.w + d.w;
    ((float4*)g_val1[i])[pos] = v;
}

// CSR-ordered val2 = ssrc2[src] + edot2[eid]
__global__ void k_prep2() {
    int i = blockIdx.x / EB;
    int bx = blockIdx.x % EB;
    int pos = bx * 256 + threadIdx.x;
    if (pos >= Ee) return;
    int2 c = g_csr[i][pos];
    g_val2[i][pos] = g_ssrc2[i][c.x] + g_edot2[i][c.y];
}

// ---------------- gather layer 1 (+ fused layer-2 logits) -----------------------
__global__ void k_gather1(const float* __restrict__ b1) {
    int i = blockIdx.x / GB;
    int bx = blockIdx.x % GB;
    int warp = threadIdx.x >> 5;
    int n = bx * 8 + warp;
    if (n >= Nn) return;
    int lane = threadIdx.x & 31;
    int hh = lane >> 3;

    const float* hbase = g_h[i];
    const int2* csr = g_csr[i];
    const float* val1 = g_val1[i];

    float sdv = g_sdst[i][n * 4 + hh];
    float alv = g_aloop[i][n * 4 + hh];

    float4 acc = ((const float4*)(hbase + (size_t)n * HDim))[lane];
    float den = 1.f;

    int k = g_rowptr[i][n];
    int end = g_rowptr[i][n + 1];
#pragma unroll 1
    for (; k + 1 < end; k += 2) {
        int s0 = csr[k].x;
        int s1 = csr[k + 1].x;
        float4 h0 = ((const float4*)(hbase + (size_t)s0 * HDim))[lane];
        float4 h1 = ((const float4*)(hbase + (size_t)s1 * HDim))[lane];
        float a0 = val1[(size_t)k * 4 + hh] + sdv;
        float a1 = val1[(size_t)(k + 1) * 4 + hh] + sdv;
        a0 = a0 > 0.f ? a0 : 0.2f * a0;
        a1 = a1 > 0.f ? a1 : 0.2f * a1;
        float x0 = __expf(a0 - alv);
        float x1 = __expf(a1 - alv);
        den += x0 + x1;
        acc.x += x0 * h0.x + x1 * h1.x;
        acc.y += x0 * h0.y + x1 * h1.y;
        acc.z += x0 * h0.z + x1 * h1.z;
        acc.w += x0 * h0.w + x1 * h1.w;
    }
    if (k < end) {
        int s0 = csr[k].x;
        float4 h0 = ((const float4*)(hbase + (size_t)s0 * HDim))[lane];
        float a0 = val1[(size_t)k * 4 + hh] + sdv;
        a0 = a0 > 0.f ? a0 : 0.2f * a0;
        float x0 = __expf(a0 - alv);
        den += x0;
        acc.x += x0 * h0.x; acc.y += x0 * h0.y; acc.z += x0 * h0.z; acc.w += x0 * h0.w;
    }

    float inv = 1.f / (den + 1e-16f);
    float4 bv = ((const float4*)(b1 + i * HDim))[lane];
    float4 v;
    v.x = acc.x * inv + bv.x;  v.x = v.x > 0.f ? v.x : (__expf(v.x) - 1.f);
    v.y = acc.y * inv + bv.y;  v.y = v.y > 0.f ? v.y : (__expf(v.y) - 1.f);
    v.z = acc.z * inv + bv.z;  v.z = v.z > 0.f ? v.z : (__expf(v.z) - 1.f);
    v.w = acc.w * inv + bv.w;  v.w = v.w > 0.f ? v.w : (__expf(v.w) - 1.f);
    ((float4*)(g_x2[i] + (size_t)n * HDim))[lane] = v;

    float4 wa = ((const float4*)g_wa2[i])[lane];
    float4 wd = ((const float4*)g_wd2[i])[lane];
    float ss = v.x * wa.x + v.y * wa.y + v.z * wa.z + v.w * wa.w;
    float sd = v.x * wd.x + v.y * wd.y + v.z * wd.z + v.w * wd.w;
#pragma unroll
    for (int o = 16; o > 0; o >>= 1) {
        ss += __shfl_xor_sync(0xffffffffu, ss, o);
        sd += __shfl_xor_sync(0xffffffffu, sd, o);
    }
    if (lane == 0) {
        g_ssrc2[i][n] = ss;
        g_sdst2[i][n] = sd;
        float a = ss + sd + g_edl2[i];
        a = a > 0.f ? a : 0.2f * a;
        g_aloop2[i][n] = a;
    }
}

// ---------------- tf32 GEMM: g_h[i] = g_x2[i] @ W2[i] ---------------------------
__global__ void gemm_tf32(const float* __restrict__ W2) {
    int ty = blockIdx.x / MB;
    int bx = blockIdx.x % MB;
    const float* X = g_x2[ty];
    float* Y = g_h[ty];
    const float* W = W2 + (size_t)ty * HDim * HDim;
    __shared__ uint32_t Xs[128][36];
    __shared__ uint32_t Ws[32][136];
    int tid = threadIdx.x;
    int wid = tid >> 5, lane = tid & 31;
    int wm = wid & 3, wn = wid >> 2;
    int g = lane >> 2, c = lane & 3;
    int m0 = bx * 128;

    float acc[2][8][4];
#pragma unroll
    for (int mf = 0; mf < 2; mf++)
#pragma unroll
        for (int nf = 0; nf < 8; nf++)
#pragma unroll
            for (int q = 0; q < 4; q++) acc[mf][nf][q] = 0.f;

    for (int kt = 0; kt < 4; kt++) {
#pragma unroll
        for (int it = 0; it < 4; it++) {
            int idx = tid + it * 256;
            int row = idx >> 3;
            int q4 = idx & 7;
            int n = m0 + row;
            float4 xv = (n < Nn) ? ((const float4*)(X + (size_t)n * 128 + kt * 32))[q4]
                                 : make_float4(0.f, 0.f, 0.f, 0.f);
            Xs[row][q4 * 4 + 0] = f2tf32(xv.x);
            Xs[row][q4 * 4 + 1] = f2tf32(xv.y);
            Xs[row][q4 * 4 + 2] = f2tf32(xv.z);
            Xs[row][q4 * 4 + 3] = f2tf32(xv.w);
        }
#pragma unroll
        for (int it = 0; it < 4; it++) {
            int idx = tid + it * 256;
            int kk = idx >> 5;
            int q4 = idx & 31;
            float4 wv = ((const float4*)(W + (size_t)(kt * 32 + kk) * 128))[q4];
            Ws[kk][q4 * 4 + 0] = f2tf32(wv.x);
            Ws[kk][q4 * 4 + 1] = f2tf32(wv.y);
            Ws[kk][q4 * 4 + 2] = f2tf32(wv.z);
            Ws[kk][q4 * 4 + 3] = f2tf32(wv.w);
        }
        __syncthreads();
#pragma unroll
        for (int ks = 0; ks < 4; ks++) {
            int k0 = ks * 8;
            uint32_t a[2][4], b[8][2];
#pragma unroll
            for (int mf = 0; mf < 2; mf++) {
                int row = wm * 32 + mf * 16;
                a[mf][0] = Xs[row + g][k0 + c];
                a[mf][1] = Xs[row + g + 8][k0 + c];
                a[mf][2] = Xs[row + g][k0 + c + 4];
                a[mf][3] = Xs[row + g + 8][k0 + c + 4];
            }
#pragma unroll
            for (int nf = 0; nf < 8; nf++) {
                int col = wn * 64 + nf * 8 + g;
                b[nf][0] = Ws[k0 + c][col];
                b[nf][1] = Ws[k0 + c + 4][col];
            }
#pragma unroll
            for (int mf = 0; mf < 2; mf++)
#pragma unroll
                for (int nf = 0; nf < 8; nf++)
                    MMA_TF32(acc[mf][nf], a[mf], b[nf]);
        }
        __syncthreads();
    }
#pragma unroll
    for (int mf = 0; mf < 2; mf++) {
#pragma unroll
        for (int nf = 0; nf < 8; nf++) {
            int row0 = m0 + wm * 32 + mf * 16 + g;
            int col = wn * 64 + nf * 8 + c * 2;
            if (row0 < Nn)
                *(float2*)(Y + (size_t)row0 * 128 + col) = make_float2(acc[mf][nf][0], acc[mf][nf][1]);
            int row1 = row0 + 8;
            if (row1 < Nn)
                *(float2*)(Y + (size_t)row1 * 128 + col) = make_float2(acc[mf][nf][2], acc[mf][nf][3]);
        }
    }
}

// ---------------- gather layer 2 (per type) --------------------------------------
__global__ void k_gather2(const float* __restrict__ b2) {
    int i = blockIdx.x / GB;
    int bx = blockIdx.x % GB;
    int warp = threadIdx.x >> 5;
    int n = bx * 8 + warp;
    if (n >= Nn) return;
    int lane = threadIdx.x & 31;

    const float* hbase = g_h[i];
    const int2* csr = g_csr[i];
    const float* val2 = g_val2[i];

    float sdv = g_sdst2[i][n];
    float alv = g_aloop2[i][n];

    float4 acc = ((const float4*)(hbase + (size_t)n * HDim))[lane];
    float den = 1.f;

    int k = g_rowptr[i][n];
    int end = g_rowptr[i][n + 1];
#pragma unroll 1
    for (; k + 1 < end; k += 2) {
        int s0 = csr[k].x;
        int s1 = csr[k + 1].x;
        float4 h0 = ((const float4*)(hbase + (size_t)s0 * HDim))[lane];
        float4 h1 = ((const float4*)(hbase + (size_t)s1 * HDim))[lane];
        float a0 = val2[k] + sdv;
        float a1 = val2[k + 1] + sdv;
        a0 = a0 > 0.f ? a0 : 0.2f * a0;
        a1 = a1 > 0.f ? a1 : 0.2f * a1;
        float x0 = __expf(a0 - alv);
        float x1 = __expf(a1 - alv);
        den += x0 + x1;
        acc.x += x0 * h0.x + x1 * h1.x;
        acc.y += x0 * h0.y + x1 * h1.y;
        acc.z += x0 * h0.z + x1 * h1.z;
        acc.w += x0 * h0.w + x1 * h1.w;
    }
    if (k < end) {
        int s0 = csr[k].x;
        float4 h0 = ((const float4*)(hbase + (size_t)s0 * HDim))[lane];
        float a0 = val2[k] + sdv;
        a0 = a0 > 0.f ? a0 : 0.2f * a0;
        float x0 = __expf(a0 - alv);
        den += x0;
        acc.x += x0 * h0.x; acc.y += x0 * h0.y; acc.z += x0 * h0.z; acc.w += x0 * h0.w;
    }

    float inv = 1.f / (den + 1e-16f);
    float w = g_wts[i];
    float4 bv = ((const float4*)(b2 + i * HDim))[lane];
    float4 v;
    v.x = (acc.x * inv + bv.x) * w;
    v.y = (acc.y * inv + bv.y) * w;
    v.z = (acc.z * inv + bv.z) * w;
    v.w = (acc.w * inv + bv.w) * w;
    ((float4*)(g_x2[i] + (size_t)n * HDim))[lane] = v;
}

// combine 3 weighted type outputs + fused pooling scores (warp == one node)
__global__ void k_combine(const float* __restrict__ pW, const float* __restrict__ pb) {
    int idx = blockIdx.x * 256 + threadIdx.x;
    if (idx >= Nn * 32) return;
    float4 a = ((const float4*)g_x2[0])[idx];
    float4 b = ((const float4*)g_x2[1])[idx];
    float4 c = ((const float4*)g_x2[2])[idx];
    float4 v;
    v.x = a.x + b.x + c.x;
    v.y = a.y + b.y + c.y;
    v.z = a.z + b.z + c.z;
    v.w = a.w + b.w + c.w;
    ((float4*)g_acc)[idx] = v;
    int lane = threadIdx.x & 31;
    float4 w = ((const float4*)pW)[lane];
    float s = v.x * w.x + v.y * w.y + v.z * w.z + v.w * w.w;
#pragma unroll
    for (int o = 16; o > 0; o >>= 1) s += __shfl_xor_sync(0xffffffffu, s, o);
    int n = idx >> 5;
    if (lane == 0 && n >= Rr) g_scores[n - Rr] = s + pb[0];
}

// ---------------- pooling ---------------------------------------------------------
__global__ void k_stats(const int* __restrict__ mask) {
    int r = blockIdx.x; int t = threadIdx.x;
    __shared__ float red[256];
    __shared__ int redi[256];
    const int* mrow = mask + (size_t)r * Vv;
    float mx = -3.0e38f;
    for (int v = t; v < Vv; v += 256) if (mrow[v]) mx = fmaxf(mx, g_scores[v]);
    red[t] = mx; __syncthreads();
    for (int s = 128; s > 0; s >>= 1) { if (t < s) red[t] = fmaxf(red[t], red[t + s]); __syncthreads(); }
    float m = red[0]; __syncthreads();
    float sm = 0.f; int c = 0;
    for (int v = t; v < Vv; v += 256)
        if (mrow[v]) { sm += __expf(g_scores[v] - m); c++; }
    red[t] = sm; redi[t] = c; __syncthreads();
    for (int s = 128; s > 0; s >>= 1) {
        if (t < s) { red[t] += red[t + s]; redi[t] += redi[t + s]; }
        __syncthreads();
    }
    if (t == 0) { g_pmax[r] = m; g_pden[r] = red[0]; g_pcnt[r] = redi[0]; }
    if (t < HDim) g_pooled[r * HDim + t] = 0.f;
}

__global__ void k_pooled(const int* __restrict__ mask) {
    __shared__ float aws[64 * 128];
    int t = threadIdx.x;
    int vb = blockIdx.x * 128;
    int nv = Vv - vb; if (nv > 128) nv = 128;
    for (int idx = t; idx < 64 * 128; idx += 256) {
        int r = idx >> 7, v = idx & 127;
        float aw = 0.f;
        if (v < nv) {
            int mv = mask[(size_t)r * Vv + vb + v];
            if (mv && g_pcnt[r] > 0)
                aw = __expf(g_scores[vb + v] - g_pmax[r]) / g_pden[r];
        }
        aws[idx] = aw;
    }
    __syncthreads();
    int rg = t >> 7, c = t & 127;
    float acc[32];
#pragma unroll
    for (int rr = 0; rr < 32; rr++) acc[rr] = 0.f;
    for (int v = 0; v < nv; v++) {
        float vx = g_acc[(size_t)(Rr + vb + v) * HDim + c];
#pragma unroll
        for (int rr = 0; rr < 32; rr++) acc[rr] += aws[(rg * 32 + rr) * 128 + v] * vx;
    }
    for (int rr = 0; rr < 32; rr++)
        atomicAdd(&g_pooled[(rg * 32 + rr) * 128 + c], acc[rr]);
}

// ---------------- readout MLP ------------------------------------------------------
__global__ void k_q1(const float* __restrict__ Wo1, const float* __restrict__ bo1) {
    __shared__ float comb[256];
    int r = blockIdx.x, t = threadIdx.x;
    comb[t] = g_acc[r * HDim + t];
    comb[128 + t] = g_pooled[r * HDim + t];
    __syncthreads();
    float a = bo1[t];
    for (int k = 0; k < 256; k++) a += comb[k] * Wo1[k * 128 + t];
    g_q1[r * 128 + t] = fmaxf(a, 0.f);
}

__global__ void k_q2(const float* __restrict__ Wo2, const float* __restrict__ bo2) {
    __shared__ float q[128];
    int r = blockIdx.x, t = threadIdx.x;
    q[t] = g_q1[r * 128 + t]; q[64 + t] = g_q1[r * 128 + 64 + t];
    __syncthreads();
    float a = bo2[t];
    for (int k = 0; k < 128; k++) a += q[k] * Wo2[k * 64 + t];
    g_q2[r * 64 + t] = fmaxf(a, 0.f);
}

__global__ void k_q3(const float* __restrict__ Wo3, const float* __restrict__ bo3,
                     const float* __restrict__ eta, float* __restrict__ out, int out_size) {
    __shared__ float q[64];
    int r = blockIdx.x, t = threadIdx.x;
    q[t] = g_q2[r * 64 + t]; q[32 + t] = g_q2[r * 64 + 32 + t];
    __syncthreads();
    if (t < 16) {
        float a = bo3[t];
        for (int k = 0; k < 64; k++) a += q[k] * Wo3[k * 16 + t];
        int oi = r * 16 + t;
        if (oi < out_size) out[oi] = a;
    }
    if (r == 0 && t >= 16 && t < 19) {
        int oi = 1024 + (t - 16);
        if (oi < out_size) out[oi] = eta[t - 16];
    }
}

// ---------------- launch ------------------------------------------------------------
extern "C" void kernel_launch(void* const* d_in, const int* in_sizes, int n_in,
                              void* d_out, int out_size) {
    const float* nf    = (const float*)d_in[0];
    const float* ea0   = (const float*)d_in[1];
    const float* ea1   = (const float*)d_in[2];
    const float* ea2   = (const float*)d_in[3];
    const float* temb  = (const float*)d_in[4];
    const float* etg   = (const float*)d_in[5];
    const float* eta   = (const float*)d_in[6];
    const float* W1    = (const float*)d_in[7];
    const float* as1   = (const float*)d_in[8];
    const float* ad1   = (const float*)d_in[9];
    const float* We1   = (const float*)d_in[10];
    const float* ae1   = (const float*)d_in[11];
    const float* b1    = (const float*)d_in[12];
    const float* W2    = (const float*)d_in[13];
    const float* as2   = (const float*)d_in[14];
    const float* ad2   = (const float*)d_in[15];
    const float* We2   = (const float*)d_in[16];
    const float* ae2   = (const float*)d_in[17];
    const float* b2    = (const float*)d_in[18];
    const float* pW    = (const float*)d_in[19];
    const float* pb    = (const float*)d_in[20];
    const float* Wo1   = (const float*)d_in[21];
    const float* bo1   = (const float*)d_in[22];
    const float* Wo2   = (const float*)d_in[23];
    const float* bo2   = (const float*)d_in[24];
    const float* Wo3   = (const float*)d_in[25];
    const float* bo3   = (const float*)d_in[26];
    const int* ntype   = (const int*)d_in[27];
    const int* ei0     = (const int*)d_in[28];
    const int* ei1     = (const int*)d_in[29];
    const int* ei2     = (const int*)d_in[30];
    const int* mask    = (const int*)d_in[31];
    float* out = (float*)d_out;

    static cudaStream_t sCsr = nullptr;
    static cudaEvent_t evRoot = nullptr, evCsr = nullptr;
    if (sCsr == nullptr) {
        cudaStreamCreateWithFlags(&sCsr, cudaStreamNonBlocking);
        cudaEventCreateWithFlags(&evRoot, cudaEventDisableTiming);
        cudaEventCreateWithFlags(&evCsr, cudaEventDisableTiming);
    }

    k_init<<<586, 256>>>();
    cudaEventRecord(evRoot, 0);
    cudaStreamWaitEvent(sCsr, evRoot, 0);

    // Branch A (forked stream): CSR build
    { dim3 g(586, 3); k_deg<<<g, 1024, 0, sCsr>>>(ei0, ei1, ei2); }
    { dim3 g(NCHUNK, 3); k_partial<<<g, 512, 0, sCsr>>>(); }
    k_scanb<<<1, 32, 0, sCsr>>>();
    { dim3 g(NCHUNK, 3); k_scan2<<<g, 512, 0, sCsr>>>(); }
    { dim3 g(586, 3); k_fill<<<g, 1024, 0, sCsr>>>(ei0, ei1, ei2); }
    cudaEventRecord(evCsr, sCsr);

    // Branch B (default stream): setup + edge dots + projections
    { dim3 g(147, 3); k_easum<<<g, 256>>>(ea0, ea1, ea2); }
    k_setup<<<1, 256>>>(temb, etg, eta, W1, We1, ae1, We2, ae2,
                        as1, ad1, W2, as2, ad2);
    k_edot<<<3 * EB, 256>>>(ea0, ea1, ea2);
    { dim3 g(12500, 3); k_projA<<<g, 128>>>(nf, ntype, W1); }
    k_sattn1<<<196, 256>>>(nf, ntype);

    // join
    cudaStreamWaitEvent(0, evCsr, 0);

    k_prep1<<<3 * EB, 256>>>();
    k_gather1<<<3 * GB, 256>>>(b1);
    gemm_tf32<<<3 * MB, 256>>>(W2);
    k_prep2<<<3 * EB, 256>>>();
    k_gather2<<<3 * GB, 256>>>(b2);
    k_combine<<<6250, 256>>>(pW, pb);

    k_stats<<<64, 256>>>(mask);
    k_pooled<<<391, 256>>>(mask);
    k_q1<<<64, 128>>>(Wo1, bo1);
    k_q2<<<64, 64>>>(Wo2, bo2);
    k_q3<<<64, 32>>>(Wo3, bo3, eta, out, out_size);
}

// round 13
// speedup vs baseline: 1.0789x; 1.0789x over previous
#include <cuda_runtime.h>
#include <math.h>
#include <stdint.h>

#define Nn 50000
#define Ee 600000
#define Rr 64
#define Vv 49936
#define HDim 128
#define NHEAD 4
#define EDim 8
#define NCHUNK 98
#define GB 6250    // gather blocks per type
#define EB 2344    // edge blocks per type
#define MB 391     // gemm blocks per type

// ---------------- scratch ----------------------------------------------------
__device__ float g_h[3][(size_t)Nn * HDim];
__device__ float g_x2[3][(size_t)Nn * HDim];
__device__ float g_acc[(size_t)Nn * HDim];
__device__ float g_ssrc[3][Nn * NHEAD];
__device__ float g_sdst[3][Nn * NHEAD];
__device__ float g_aloop[3][Nn * NHEAD];
__device__ float g_ssrc2[3][Nn];
__device__ float g_sdst2[3][Nn];
__device__ float g_aloop2[3][Nn];
__device__ int   g_deg[3][Nn];
__device__ int   g_cursor[3][Nn];
__device__ int   g_rowptr[3][Nn + 1];
__device__ int   g_bsum[3][NCHUNK];
__device__ int2  g_csr[3][Ee];          // packed (src, eid)
__device__ float g_edot1[3][(size_t)Ee * 4];
__device__ float g_edot2[3][Ee];
__device__ float g_scores[Vv];
__device__ float g_pmax[Rr], g_pden[Rr];
__device__ int   g_pcnt[Rr];
__device__ float g_pooled[Rr * HDim];
__device__ float g_gate[3], g_wts[3];
__device__ float g_Wt[3][2][HDim];
__device__ float g_v1[3][NHEAD][EDim];
__device__ float g_v2[3][EDim];
__device__ float g_edl1[3][NHEAD];
__device__ float g_edl2[3];
__device__ float g_easum[3][EDim];
__device__ float g_was1[3][NHEAD][9];
__device__ float g_wad1[3][NHEAD][9];
__device__ float g_cA1[3][2][NHEAD];
__device__ float g_cD1[3][2][NHEAD];
__device__ float g_wa2[3][HDim];
__device__ float g_wd2[3][HDim];

__device__ __forceinline__ uint32_t f2tf32(float f) {
    uint32_t u; asm("cvt.rna.tf32.f32 %0, %1;" : "=r"(u) : "f"(f)); return u;
}

#define MMA_TF32(d, a, b) \
    asm volatile("mma.sync.aligned.m16n8k8.row.col.f32.tf32.tf32.f32 " \
        "{%0,%1,%2,%3}, {%4,%5,%6,%7}, {%8,%9}, {%0,%1,%2,%3};" \
        : "+f"(d[0]), "+f"(d[1]), "+f"(d[2]), "+f"(d[3]) \
        : "r"(a[0]), "r"(a[1]), "r"(a[2]), "r"(a[3]), "r"(b[0]), "r"(b[1]))

// ---------------- init + setup ------------------------------------------------
__global__ void k_init() {
    int i = blockIdx.x * 256 + threadIdx.x;
    if (i < 3 * Nn) ((int*)g_deg)[i] = 0;
    if (i < 24) ((float*)g_easum)[i] = 0.f;
}

__global__ void k_easum(const float* __restrict__ ea0, const float* __restrict__ ea1,
                        const float* __restrict__ ea2) {
    const float* ea = blockIdx.y == 0 ? ea0 : (blockIdx.y == 1 ? ea1 : ea2);
    __shared__ float s[EDim];
    if (threadIdx.x < EDim) s[threadIdx.x] = 0.f;
    __syncthreads();
    float loc[EDim];
#pragma unroll
    for (int k = 0; k < EDim; k++) loc[k] = 0.f;
    int base = blockIdx.x * 4096;
    int lim = base + 4096; if (lim > Ee) lim = Ee;
    for (int e = base + threadIdx.x; e < lim; e += 256) {
        const float4* p = (const float4*)(ea + (size_t)e * 8);
        float4 a = p[0], b = p[1];
        loc[0] += a.x; loc[1] += a.y; loc[2] += a.z; loc[3] += a.w;
        loc[4] += b.x; loc[5] += b.y; loc[6] += b.z; loc[7] += b.w;
    }
#pragma unroll
    for (int k = 0; k < EDim; k++) atomicAdd(&s[k], loc[k]);
    __syncthreads();
    if (threadIdx.x < EDim) atomicAdd(&g_easum[blockIdx.y][threadIdx.x], s[threadIdx.x]);
}

__global__ void k_setup(const float* __restrict__ temb, const float* __restrict__ etg,
                        const float* __restrict__ eta, const float* __restrict__ W1,
                        const float* __restrict__ We1, const float* __restrict__ ae1,
                        const float* __restrict__ We2, const float* __restrict__ ae2,
                        const float* __restrict__ as1, const float* __restrict__ ad1,
                        const float* __restrict__ W2, const float* __restrict__ as2,
                        const float* __restrict__ ad2) {
    int t = threadIdx.x;
    if (t < 3) g_gate[t] = 1.f / (1.f + __expf(-etg[t]));
    if (t == 0) {
        float m = fmaxf(eta[0], fmaxf(eta[1], eta[2]));
        float e0 = __expf(eta[0] - m), e1 = __expf(eta[1] - m), e2 = __expf(eta[2] - m);
        float s = e0 + e1 + e2;
        g_wts[0] = e0 / s; g_wts[1] = e1 / s; g_wts[2] = e2 / s;
    }
    __syncthreads();
    for (int idx = t; idx < 3 * 2 * HDim; idx += 256) {
        int i = idx / (2 * HDim); int r = idx % (2 * HDim);
        int ty = r / HDim; int j = r % HDim;
        float s = 0.f;
        for (int k = 0; k < 32; k++)
            s += temb[ty * 32 + k] * W1[i * 41 * HDim + (9 + k) * HDim + j];
        g_Wt[i][ty][j] = s;
    }
    for (int idx = t; idx < 3 * NHEAD * EDim; idx += 256) {
        int i = idx / 32; int h = (idx % 32) / 8; int k = idx % 8;
        float s = 0.f;
        for (int c = 0; c < 32; c++)
            s += We1[i * EDim * HDim + k * HDim + h * 32 + c] * ae1[i * NHEAD * 32 + h * 32 + c];
        g_v1[i][h][k] = g_gate[i] * s;
    }
    for (int idx = t; idx < 3 * EDim; idx += 256) {
        int i = idx / 8; int k = idx % 8;
        float s = 0.f;
        for (int c = 0; c < HDim; c++)
            s += We2[i * EDim * HDim + k * HDim + c] * ae2[i * HDim + c];
        g_v2[i][k] = g_gate[i] * s;
    }
    for (int idx = t; idx < 108; idx += 256) {
        int i = idx / 36; int h = (idx % 36) / 9; int k = idx % 9;
        float sa = 0.f, sd = 0.f;
        for (int c = 0; c < 32; c++) {
            float w = W1[i * 41 * HDim + k * HDim + h * 32 + c];
            sa += w * as1[i * HDim + h * 32 + c];
            sd += w * ad1[i * HDim + h * 32 + c];
        }
        g_was1[i][h][k] = sa;
        g_wad1[i][h][k] = sd;
    }
    for (int idx = t; idx < 3 * HDim; idx += 256) {
        int i = idx / HDim; int k = idx % HDim;
        float sa = 0.f, sd = 0.f;
        for (int j = 0; j < HDim; j++) {
            float w = W2[(size_t)i * HDim * HDim + k * HDim + j];
            sa += w * as2[i * HDim + j];
            sd += w * ad2[i * HDim + j];
        }
        g_wa2[i][k] = sa;
        g_wd2[i][k] = sd;
    }
    __syncthreads();
    if (t < 12) {
        int i = t / 4, h = t % 4;
        float s = 0.f;
        for (int k = 0; k < EDim; k++) s += (g_easum[i][k] / (float)Ee) * g_v1[i][h][k];
        g_edl1[i][h] = s;
    }
    if (t >= 32 && t < 35) {
        int i = t - 32;
        float s = 0.f;
        for (int k = 0; k < EDim; k++) s += (g_easum[i][k] / (float)Ee) * g_v2[i][k];
        g_edl2[i] = s;
    }
    if (t >= 64 && t < 88) {
        int r = t - 64;
        int i = r / 8; int ty = (r % 8) / 4; int h = r % 4;
        float sa = 0.f, sd = 0.f;
        for (int c = 0; c < 32; c++) {
            float w = g_Wt[i][ty][h * 32 + c];
            sa += w * as1[i * HDim + h * 32 + c];
            sd += w * ad1[i * HDim + h * 32 + c];
        }
        g_cA1[i][ty][h] = sa;
        g_cD1[i][ty][h] = sd;
    }
}

// ---------------- CSR build ----------------------------------------------------
__global__ void k_deg(const int* __restrict__ ei0, const int* __restrict__ ei1,
                      const int* __restrict__ ei2) {
    const int* ei = blockIdx.y == 0 ? ei0 : (blockIdx.y == 1 ? ei1 : ei2);
    int e = blockIdx.x * 1024 + threadIdx.x;
    if (e < Ee) atomicAdd(&g_deg[blockIdx.y][ei[Ee + e]], 1);
}

__global__ void k_partial() {
    __shared__ int s[512];
    int ty = blockIdx.y;
    int t = threadIdx.x;
    int i = blockIdx.x * 512 + t;
    s[t] = (i < Nn) ? g_deg[ty][i] : 0;
    __syncthreads();
    for (int off = 256; off > 0; off >>= 1) {
        if (t < off) s[t] += s[t + off];
        __syncthreads();
    }
    if (t == 0) g_bsum[ty][blockIdx.x] = s[0];
}

__global__ void k_scanb() {
    int t = threadIdx.x;
    if (t < 3) {
        int s = 0;
        for (int b = 0; b < NCHUNK; b++) { int v = g_bsum[t][b]; g_bsum[t][b] = s; s += v; }
    }
}

__global__ void k_scan2() {
    __shared__ int s[512];
    int ty = blockIdx.y;
    int t = threadIdx.x;
    int i = blockIdx.x * 512 + t;
    int v = (i < Nn) ? g_deg[ty][i] : 0;
    s[t] = v;
    __syncthreads();
    for (int off = 1; off < 512; off <<= 1) {
        int x = 0;
        if (t >= off) x = s[t - off];
        __syncthreads();
        s[t] += x;
        __syncthreads();
    }
    int excl = s[t] - v + g_bsum[ty][blockIdx.x];
    if (i < Nn) {
        g_rowptr[ty][i] = excl;
        g_cursor[ty][i] = excl;
        if (i == Nn - 1) g_rowptr[ty][Nn] = excl + v;
    }
}

__global__ void k_fill(const int* __restrict__ ei0, const int* __restrict__ ei1,
                       const int* __restrict__ ei2) {
    int ty = blockIdx.y;
    const int* ei = ty == 0 ? ei0 : (ty == 1 ? ei1 : ei2);
    int e = blockIdx.x * 1024 + threadIdx.x;
    if (e >= Ee) return;
    int src = ei[e], dst = ei[Ee + e];
    int pos = atomicAdd(&g_cursor[ty][dst], 1);
    g_csr[ty][pos] = make_int2(src, e);
}

// mask row counts + pooled zero (runs on forked stream; also warms mask in L2)
__global__ void k_maskcnt(const int* __restrict__ mask) {
    int r = blockIdx.x; int t = threadIdx.x;
    __shared__ int redi[256];
    const int* mrow = mask + (size_t)r * Vv;
    int c = 0;
    for (int v = t; v < Vv; v += 256) if (mrow[v]) c++;
    redi[t] = c; __syncthreads();
    for (int s = 128; s > 0; s >>= 1) {
        if (t < s) redi[t] += redi[t + s];
        __syncthreads();
    }
    if (t == 0) g_pcnt[r] = redi[0];
    if (t < HDim) g_pooled[r * HDim + t] = 0.f;
}

// per-edge attention edge-term dots
__global__ void k_edot(const float* __restrict__ ea0, const float* __restrict__ ea1,
                       const float* __restrict__ ea2) {
    int i = blockIdx.x / EB;
    int bx = blockIdx.x % EB;
    const float* ea = i == 0 ? ea0 : (i == 1 ? ea1 : ea2);
    int e = bx * 256 + threadIdx.x;
    if (e >= Ee) return;
    const float4* p = (const float4*)(ea + (size_t)e * 8);
    float4 a0 = p[0], a1 = p[1];
    float4 d1;
    {
        const float* v = g_v1[i][0];
        d1.x = a0.x*v[0]+a0.y*v[1]+a0.z*v[2]+a0.w*v[3]+a1.x*v[4]+a1.y*v[5]+a1.z*v[6]+a1.w*v[7];
    }
    {
        const float* v = g_v1[i][1];
        d1.y = a0.x*v[0]+a0.y*v[1]+a0.z*v[2]+a0.w*v[3]+a1.x*v[4]+a1.y*v[5]+a1.z*v[6]+a1.w*v[7];
    }
    {
        const float* v = g_v1[i][2];
        d1.z = a0.x*v[0]+a0.y*v[1]+a0.z*v[2]+a0.w*v[3]+a1.x*v[4]+a1.y*v[5]+a1.z*v[6]+a1.w*v[7];
    }
    {
        const float* v = g_v1[i][3];
        d1.w = a0.x*v[0]+a0.y*v[1]+a0.z*v[2]+a0.w*v[3]+a1.x*v[4]+a1.y*v[5]+a1.z*v[6]+a1.w*v[7];
    }
    ((float4*)g_edot1[i])[e] = d1;
    const float* v = g_v2[i];
    g_edot2[i][e] = a0.x*v[0]+a0.y*v[1]+a0.z*v[2]+a0.w*v[3]+a1.x*v[4]+a1.y*v[5]+a1.z*v[6]+a1.w*v[7];
}

// ---------------- layer 1: h projection ----------------------------------------
__global__ void k_projA(const float* __restrict__ nf, const int* __restrict__ ntype,
                        const float* __restrict__ W1) {
    int i = blockIdx.y;
    const float* W1i = W1 + (size_t)i * 41 * HDim;
    int j = threadIdx.x;
    float w[9];
#pragma unroll
    for (int k = 0; k < 9; k++) w[k] = W1i[k * HDim + j];
    float wt0 = g_Wt[i][0][j], wt1 = g_Wt[i][1][j];
    float* hout = g_h[i];
    int nb = blockIdx.x * 4;
#pragma unroll
    for (int nn = 0; nn < 4; nn++) {
        int n = nb + nn;
        const float* row = nf + (size_t)n * 9;
        float acc = ntype[n] ? wt1 : wt0;
#pragma unroll
        for (int k = 0; k < 9; k++) acc += row[k] * w[k];
        hout[(size_t)n * HDim + j] = acc;
    }
}

__global__ void k_sattn1(const float* __restrict__ nf, const int* __restrict__ ntype) {
    int n = blockIdx.x * 256 + threadIdx.x;
    if (n >= Nn) return;
    float f[9];
#pragma unroll
    for (int k = 0; k < 9; k++) f[k] = nf[(size_t)n * 9 + k];
    int ty = ntype[n];
#pragma unroll
    for (int i = 0; i < 3; i++) {
#pragma unroll
        for (int h = 0; h < 4; h++) {
            float ss = g_cA1[i][ty][h];
            float sd = g_cD1[i][ty][h];
#pragma unroll
            for (int k = 0; k < 9; k++) {
                ss += f[k] * g_was1[i][h][k];
                sd += f[k] * g_wad1[i][h][k];
            }
            g_ssrc[i][n * 4 + h] = ss;
            g_sdst[i][n * 4 + h] = sd;
            float a = ss + sd + g_edl1[i][h];
            a = a > 0.f ? a : 0.2f * a;
            g_aloop[i][n * 4 + h] = a;
        }
    }
}

// ---------------- gather layer 1 (+ fused layer-2 logits), MLP-2, int2 CSR ------
__global__ void k_gather1(const float* __restrict__ b1) {
    int i = blockIdx.x / GB;
    int bx = blockIdx.x % GB;
    int warp = threadIdx.x >> 5;
    int n = bx * 8 + warp;
    if (n >= Nn) return;
    int lane = threadIdx.x & 31;
    int hh = lane >> 3;

    const float* hbase = g_h[i];
    const float* ssrc = g_ssrc[i];
    const int2* csr = g_csr[i];
    const float* ed1 = g_edot1[i];

    float sdv = g_sdst[i][n * 4 + hh];
    float alv = g_aloop[i][n * 4 + hh];

    float4 acc = ((const float4*)(hbase + (size_t)n * HDim))[lane];
    float den = 1.f;

    int k = g_rowptr[i][n];
    int end = g_rowptr[i][n + 1];
#pragma unroll 1
    for (; k + 1 < end; k += 2) {
        int2 c0 = csr[k];
        int2 c1 = csr[k + 1];
        float4 h0 = ((const float4*)(hbase + (size_t)c0.x * HDim))[lane];
        float4 h1 = ((const float4*)(hbase + (size_t)c1.x * HDim))[lane];
        float a0 = ssrc[c0.x * 4 + hh] + sdv + ed1[(size_t)c0.y * 4 + hh];
        float a1 = ssrc[c1.x * 4 + hh] + sdv + ed1[(size_t)c1.y * 4 + hh];
        a0 = a0 > 0.f ? a0 : 0.2f * a0;
        a1 = a1 > 0.f ? a1 : 0.2f * a1;
        float x0 = __expf(a0 - alv);
        float x1 = __expf(a1 - alv);
        den += x0 + x1;
        acc.x += x0 * h0.x + x1 * h1.x;
        acc.y += x0 * h0.y + x1 * h1.y;
        acc.z += x0 * h0.z + x1 * h1.z;
        acc.w += x0 * h0.w + x1 * h1.w;
    }
    if (k < end) {
        int2 c0 = csr[k];
        float4 h0 = ((const float4*)(hbase + (size_t)c0.x * HDim))[lane];
        float a0 = ssrc[c0.x * 4 + hh] + sdv + ed1[(size_t)c0.y * 4 + hh];
        a0 = a0 > 0.f ? a0 : 0.2f * a0;
        float x0 = __expf(a0 - alv);
        den += x0;
        acc.x += x0 * h0.x; acc.y += x0 * h0.y; acc.z += x0 * h0.z; acc.w += x0 * h0.w;
    }

    float inv = 1.f / (den + 1e-16f);
    float4 bv = ((const float4*)(b1 + i * HDim))[lane];
    float4 v;
    v.x = acc.x * inv + bv.x;  v.x = v.x > 0.f ? v.x : (__expf(v.x) - 1.f);
    v.y = acc.y * inv + bv.y;  v.y = v.y > 0.f ? v.y : (__expf(v.y) - 1.f);
    v.z = acc.z * inv + bv.z;  v.z = v.z > 0.f ? v.z : (__expf(v.z) - 1.f);
    v.w = acc.w * inv + bv.w;  v.w = v.w > 0.f ? v.w : (__expf(v.w) - 1.f);
    ((float4*)(g_x2[i] + (size_t)n * HDim))[lane] = v;

    float4 wa = ((const float4*)g_wa2[i])[lane];
    float4 wd = ((const float4*)g_wd2[i])[lane];
    float ss = v.x * wa.x + v.y * wa.y + v.z * wa.z + v.w * wa.w;
    float sd = v.x * wd.x + v.y * wd.y + v.z * wd.z + v.w * wd.w;
#pragma unroll
    for (int o = 16; o > 0; o >>= 1) {
        ss += __shfl_xor_sync(0xffffffffu, ss, o);
        sd += __shfl_xor_sync(0xffffffffu, sd, o);
    }
    if (lane == 0) {
        g_ssrc2[i][n] = ss;
        g_sdst2[i][n] = sd;
        float a = ss + sd + g_edl2[i];
        a = a > 0.f ? a : 0.2f * a;
        g_aloop2[i][n] = a;
    }
}

// ---------------- tf32 GEMM: g_h[i] = g_x2[i] @ W2[i] ---------------------------
__global__ void gemm_tf32(const float* __restrict__ W2) {
    int ty = blockIdx.x / MB;
    int bx = blockIdx.x % MB;
    const float* X = g_x2[ty];
    float* Y = g_h[ty];
    const float* W = W2 + (size_t)ty * HDim * HDim;
    __shared__ uint32_t Xs[128][36];
    __shared__ uint32_t Ws[32][136];
    int tid = threadIdx.x;
    int wid = tid >> 5, lane = tid & 31;
    int wm = wid & 3, wn = wid >> 2;
    int g = lane >> 2, c = lane & 3;
    int m0 = bx * 128;

    float acc[2][8][4];
#pragma unroll
    for (int mf = 0; mf < 2; mf++)
#pragma unroll
        for (int nf = 0; nf < 8; nf++)
#pragma unroll
            for (int q = 0; q < 4; q++) acc[mf][nf][q] = 0.f;

    for (int kt = 0; kt < 4; kt++) {
#pragma unroll
        for (int it = 0; it < 4; it++) {
            int idx = tid + it * 256;
            int row = idx >> 3;
            int q4 = idx & 7;
            int n = m0 + row;
            float4 xv = (n < Nn) ? ((const float4*)(X + (size_t)n * 128 + kt * 32))[q4]
                                 : make_float4(0.f, 0.f, 0.f, 0.f);
            Xs[row][q4 * 4 + 0] = f2tf32(xv.x);
            Xs[row][q4 * 4 + 1] = f2tf32(xv.y);
            Xs[row][q4 * 4 + 2] = f2tf32(xv.z);
            Xs[row][q4 * 4 + 3] = f2tf32(xv.w);
        }
#pragma unroll
        for (int it = 0; it < 4; it++) {
            int idx = tid + it * 256;
            int kk = idx >> 5;
            int q4 = idx & 31;
            float4 wv = ((const float4*)(W + (size_t)(kt * 32 + kk) * 128))[q4];
            Ws[kk][q4 * 4 + 0] = f2tf32(wv.x);
            Ws[kk][q4 * 4 + 1] = f2tf32(wv.y);
            Ws[kk][q4 * 4 + 2] = f2tf32(wv.z);
            Ws[kk][q4 * 4 + 3] = f2tf32(wv.w);
        }
        __syncthreads();
#pragma unroll
        for (int ks = 0; ks < 4; ks++) {
            int k0 = ks * 8;
            uint32_t a[2][4], b[8][2];
#pragma unroll
            for (int mf = 0; mf < 2; mf++) {
                int row = wm * 32 + mf * 16;
                a[mf][0] = Xs[row + g][k0 + c];
                a[mf][1] = Xs[row + g + 8][k0 + c];
                a[mf][2] = Xs[row + g][k0 + c + 4];
                a[mf][3] = Xs[row + g + 8][k0 + c + 4];
            }
#pragma unroll
            for (int nf = 0; nf < 8; nf++) {
                int col = wn * 64 + nf * 8 + g;
                b[nf][0] = Ws[k0 + c][col];
                b[nf][1] = Ws[k0 + c + 4][col];
            }
#pragma unroll
            for (int mf = 0; mf < 2; mf++)
#pragma unroll
                for (int nf = 0; nf < 8; nf++)
                    MMA_TF32(acc[mf][nf], a[mf], b[nf]);
        }
        __syncthreads();
    }
#pragma unroll
    for (int mf = 0; mf < 2; mf++) {
#pragma unroll
        for (int nf = 0; nf < 8; nf++) {
            int row0 = m0 + wm * 32 + mf * 16 + g;
            int col = wn * 64 + nf * 8 + c * 2;
            if (row0 < Nn)
                *(float2*)(Y + (size_t)row0 * 128 + col) = make_float2(acc[mf][nf][0], acc[mf][nf][1]);
            int row1 = row0 + 8;
            if (row1 < Nn)
                *(float2*)(Y + (size_t)row1 * 128 + col) = make_float2(acc[mf][nf][2], acc[mf][nf][3]);
        }
    }
}

// ---------------- gather layer 2 (per type), MLP-2, int2 CSR ---------------------
__global__ void k_gather2(const float* __restrict__ b2) {
    int i = blockIdx.x / GB;
    int bx = blockIdx.x % GB;
    int warp = threadIdx.x >> 5;
    int n = bx * 8 + warp;
    if (n >= Nn) return;
    int lane = threadIdx.x & 31;

    const float* hbase = g_h[i];
    const float* ssrc = g_ssrc2[i];
    const int2* csr = g_csr[i];
    const float* ed2 = g_edot2[i];

    float sdv = g_sdst2[i][n];
    float alv = g_aloop2[i][n];

    float4 acc = ((const float4*)(hbase + (size_t)n * HDim))[lane];
    float den = 1.f;

    int k = g_rowptr[i][n];
    int end = g_rowptr[i][n + 1];
#pragma unroll 1
    for (; k + 1 < end; k += 2) {
        int2 c0 = csr[k];
        int2 c1 = csr[k + 1];
        float4 h0 = ((const float4*)(hbase + (size_t)c0.x * HDim))[lane];
        float4 h1 = ((const float4*)(hbase + (size_t)c1.x * HDim))[lane];
        float a0 = ssrc[c0.x] + sdv + ed2[c0.y];
        float a1 = ssrc[c1.x] + sdv + ed2[c1.y];
        a0 = a0 > 0.f ? a0 : 0.2f * a0;
        a1 = a1 > 0.f ? a1 : 0.2f * a1;
        float x0 = __expf(a0 - alv);
        float x1 = __expf(a1 - alv);
        den += x0 + x1;
        acc.x += x0 * h0.x + x1 * h1.x;
        acc.y += x0 * h0.y + x1 * h1.y;
        acc.z += x0 * h0.z + x1 * h1.z;
        acc.w += x0 * h0.w + x1 * h1.w;
    }
    if (k < end) {
        int2 c0 = csr[k];
        float4 h0 = ((const float4*)(hbase + (size_t)c0.x * HDim))[lane];
        float a0 = ssrc[c0.x] + sdv + ed2[c0.y];
        a0 = a0 > 0.f ? a0 : 0.2f * a0;
        float x0 = __expf(a0 - alv);
        den += x0;
        acc.x += x0 * h0.x; acc.y += x0 * h0.y; acc.z += x0 * h0.z; acc.w += x0 * h0.w;
    }

    float inv = 1.f / (den + 1e-16f);
    float w = g_wts[i];
    float4 bv = ((const float4*)(b2 + i * HDim))[lane];
    float4 v;
    v.x = (acc.x * inv + bv.x) * w;
    v.y = (acc.y * inv + bv.y) * w;
    v.z = (acc.z * inv + bv.z) * w;
    v.w = (acc.w * inv + bv.w) * w;
    ((float4*)(g_x2[i] + (size_t)n * HDim))[lane] = v;
}

// combine 3 weighted type outputs + fused pooling scores (warp == one node)
__global__ void k_combine(const float* __restrict__ pW, const float* __restrict__ pb) {
    int idx = blockIdx.x * 256 + threadIdx.x;
    if (idx >= Nn * 32) return;
    float4 a = ((const float4*)g_x2[0])[idx];
    float4 b = ((const float4*)g_x2[1])[idx];
    float4 c = ((const float4*)g_x2[2])[idx];
    float4 v;
    v.x = a.x + b.x + c.x;
    v.y = a.y + b.y + c.y;
    v.z = a.z + b.z + c.z;
    v.w = a.w + b.w + c.w;
    ((float4*)g_acc)[idx] = v;
    int lane = threadIdx.x & 31;
    float4 w = ((const float4*)pW)[lane];
    float s = v.x * w.x + v.y * w.y + v.z * w.z + v.w * w.w;
#pragma unroll
    for (int o = 16; o > 0; o >>= 1) s += __shfl_xor_sync(0xffffffffu, s, o);
    int n = idx >> 5;
    if (lane == 0 && n >= Rr) g_scores[n - Rr] = s + pb[0];
}

// ---------------- pooling (max/den only; pcnt precomputed) -----------------------
__global__ void k_stats(const int* __restrict__ mask) {
    int r = blockIdx.x; int t = threadIdx.x;
    __shared__ float red[256];
    const int* mrow = mask + (size_t)r * Vv;
    float mx = -3.0e38f;
    for (int v = t; v < Vv; v += 256) if (mrow[v]) mx = fmaxf(mx, g_scores[v]);
    red[t] = mx; __syncthreads();
    for (int s = 128; s > 0; s >>= 1) { if (t < s) red[t] = fmaxf(red[t], red[t + s]); __syncthreads(); }
    float m = red[0]; __syncthreads();
    float sm = 0.f;
    for (int v = t; v < Vv; v += 256)
        if (mrow[v]) sm += __expf(g_scores[v] - m);
    red[t] = sm; __syncthreads();
    for (int s = 128; s > 0; s >>= 1) {
        if (t < s) red[t] += red[t + s];
        __syncthreads();
    }
    if (t == 0) { g_pmax[r] = m; g_pden[r] = red[0]; }
}

__global__ void k_pooled(const int* __restrict__ mask) {
    __shared__ float aws[64 * 128];
    int t = threadIdx.x;
    int vb = blockIdx.x * 128;
    int nv = Vv - vb; if (nv > 128) nv = 128;
    for (int idx = t; idx < 64 * 128; idx += 256) {
        int r = idx >> 7, v = idx & 127;
        float aw = 0.f;
        if (v < nv) {
            int mv = mask[(size_t)r * Vv + vb + v];
            if (mv && g_pcnt[r] > 0)
                aw = __expf(g_scores[vb + v] - g_pmax[r]) / g_pden[r];
        }
        aws[idx] = aw;
    }
    __syncthreads();
    int rg = t >> 7, c = t & 127;
    float acc[32];
#pragma unroll
    for (int rr = 0; rr < 32; rr++) acc[rr] = 0.f;
    for (int v = 0; v < nv; v++) {
        float vx = g_acc[(size_t)(Rr + vb + v) * HDim + c];
#pragma unroll
        for (int rr = 0; rr < 32; rr++) acc[rr] += aws[(rg * 32 + rr) * 128 + v] * vx;
    }
    for (int rr = 0; rr < 32; rr++)
        atomicAdd(&g_pooled[(rg * 32 + rr) * 128 + c], acc[rr]);
}

// ---------------- fused readout MLP (all 3 layers, one kernel) -------------------
__global__ void k_qmlp(const float* __restrict__ Wo1, const float* __restrict__ bo1,
                       const float* __restrict__ Wo2, const float* __restrict__ bo2,
                       const float* __restrict__ Wo3, const float* __restrict__ bo3,
                       const float* __restrict__ eta, float* __restrict__ out, int out_size) {
    __shared__ float comb[256];
    __shared__ float q1s[128];
    __shared__ float q2s[64];
    int r = blockIdx.x, t = threadIdx.x;   // 128 threads
    comb[t] = g_acc[r * HDim + t];
    comb[128 + t] = g_pooled[r * HDim + t];
    __syncthreads();
    float a = bo1[t];
    for (int k = 0; k < 256; k++) a += comb[k] * Wo1[k * 128 + t];
    q1s[t] = fmaxf(a, 0.f);
    __syncthreads();
    if (t < 64) {
        float a2 = bo2[t];
        for (int k = 0; k < 128; k++) a2 += q1s[k] * Wo2[k * 64 + t];
        q2s[t] = fmaxf(a2, 0.f);
    }
    __syncthreads();
    if (t < 16) {
        float a3 = bo3[t];
        for (int k = 0; k < 64; k++) a3 += q2s[k] * Wo3[k * 16 + t];
        int oi = r * 16 + t;
        if (oi < out_size) out[oi] = a3;
    }
    if (r == 0 && t >= 16 && t < 19) {
        int oi = 1024 + (t - 16);
        if (oi < out_size) out[oi] = eta[t - 16];
    }
}

// ---------------- launch ------------------------------------------------------------
extern "C" void kernel_launch(void* const* d_in, const int* in_sizes, int n_in,
                              void* d_out, int out_size) {
    const float* nf    = (const float*)d_in[0];
    const float* ea0   = (const float*)d_in[1];
    const float* ea1   = (const float*)d_in[2];
    const float* ea2   = (const float*)d_in[3];
    const float* temb  = (const float*)d_in[4];
    const float* etg   = (const float*)d_in[5];
    const float* eta   = (const float*)d_in[6];
    const float* W1    = (const float*)d_in[7];
    const float* as1   = (const float*)d_in[8];
    const float* ad1   = (const float*)d_in[9];
    const float* We1   = (const float*)d_in[10];
    const float* ae1   = (const float*)d_in[11];
    const float* b1    = (const float*)d_in[12];
    const float* W2    = (const float*)d_in[13];
    const float* as2   = (const float*)d_in[14];
    const float* ad2   = (const float*)d_in[15];
    const float* We2   = (const float*)d_in[16];
    const float* ae2   = (const float*)d_in[17];
    const float* b2    = (const float*)d_in[18];
    const float* pW    = (const float*)d_in[19];
    const float* pb    = (const float*)d_in[20];
    const float* Wo1   = (const float*)d_in[21];
    const float* bo1   = (const float*)d_in[22];
    const float* Wo2   = (const float*)d_in[23];
    const float* bo2   = (const float*)d_in[24];
    const float* Wo3   = (const float*)d_in[25];
    const float* bo3   = (const float*)d_in[26];
    const int* ntype   = (const int*)d_in[27];
    const int* ei0     = (const int*)d_in[28];
    const int* ei1     = (const int*)d_in[29];
    const int* ei2     = (const int*)d_in[30];
    const int* mask    = (const int*)d_in[31];
    float* out = (float*)d_out;

    static cudaStream_t sCsr = nullptr;
    static cudaEvent_t evRoot = nullptr, evCsr = nullptr;
    if (sCsr == nullptr) {
        cudaStreamCreateWithFlags(&sCsr, cudaStreamNonBlocking);
        cudaEventCreateWithFlags(&evRoot, cudaEventDisableTiming);
        cudaEventCreateWithFlags(&evCsr, cudaEventDisableTiming);
    }

    k_init<<<586, 256>>>();
    cudaEventRecord(evRoot, 0);
    cudaStreamWaitEvent(sCsr, evRoot, 0);

    // Branch A (forked stream): CSR build + mask precompute
    { dim3 g(586, 3); k_deg<<<g, 1024, 0, sCsr>>>(ei0, ei1, ei2); }
    { dim3 g(NCHUNK, 3); k_partial<<<g, 512, 0, sCsr>>>(); }
    k_scanb<<<1, 32, 0, sCsr>>>();
    { dim3 g(NCHUNK, 3); k_scan2<<<g, 512, 0, sCsr>>>(); }
    { dim3 g(586, 3); k_fill<<<g, 1024, 0, sCsr>>>(ei0, ei1, ei2); }
    k_maskcnt<<<64, 256, 0, sCsr>>>(mask);
    cudaEventRecord(evCsr, sCsr);

    // Branch B (default stream): setup + edge dots + projections
    { dim3 g(147, 3); k_easum<<<g, 256>>>(ea0, ea1, ea2); }
    k_setup<<<1, 256>>>(temb, etg, eta, W1, We1, ae1, We2, ae2,
                        as1, ad1, W2, as2, ad2);
    k_edot<<<3 * EB, 256>>>(ea0, ea1, ea2);
    { dim3 g(12500, 3); k_projA<<<g, 128>>>(nf, ntype, W1); }
    k_sattn1<<<196, 256>>>(nf, ntype);

    // join
    cudaStreamWaitEvent(0, evCsr, 0);

    k_gather1<<<3 * GB, 256>>>(b1);
    gemm_tf32<<<3 * MB, 256>>>(W2);
    k_gather2<<<3 * GB, 256>>>(b2);
    k_combine<<<6250, 256>>>(pW, pb);

    k_stats<<<64, 256>>>(mask);
    k_pooled<<<391, 256>>>(mask);
    k_qmlp<<<64, 128>>>(Wo1, bo1, Wo2, bo2, Wo3, bo3, eta, out, out_size);
}